// round 8
// baseline (speedup 1.0000x reference)
#include <cuda_runtime.h>
#include <cstdint>

#define L 4096
#define D 512
#define NHEADS 8
#define CH 64
#define NB 8
#define OROWS 1536   // 3 * NHEADS * CH

// Scratch (device globals: no allocation allowed)
__device__ float g_qkv[(size_t)NB * OROWS * L];      // [B][1536][L]  (q: 0..511, k: 512..1023, v: 1024..1535)
__device__ float g_ctx[NB * NHEADS * CH * CH];       // [B][H][64][64]
__device__ float g_A[NB * D * D];                    // [B][512 c][512 d]  (ctx folded into Wout)

// ---------------------------------------------------------------------------
// tf32 tensor-core helpers
// ---------------------------------------------------------------------------
__device__ __forceinline__ uint32_t f2tf(float x) {
    uint32_t r;
    asm("cvt.rna.tf32.f32 %0, %1;" : "=r"(r) : "f"(x));
    return r;
}

__device__ __forceinline__ void mma_tf32(float* c,
                                         uint32_t a0, uint32_t a1, uint32_t a2, uint32_t a3,
                                         uint32_t b0, uint32_t b1) {
    asm volatile(
        "mma.sync.aligned.m16n8k8.row.col.f32.tf32.tf32.f32 "
        "{%0,%1,%2,%3}, {%4,%5,%6,%7}, {%8,%9}, {%0,%1,%2,%3};"
        : "+f"(c[0]), "+f"(c[1]), "+f"(c[2]), "+f"(c[3])
        : "r"(a0), "r"(a1), "r"(a2), "r"(a3), "r"(b0), "r"(b1));
}

__device__ __forceinline__ uint4 tf4(float4 v) {
    return make_uint4(f2tf(v.x), f2tf(v.y), f2tf(v.z), f2tf(v.w));
}

// ---------------------------------------------------------------------------
// Kernel 1 (tf32 TC): qkv[b,o,l] = sum_d Wqkv[o,d] * x[b,l,d]
// 128(o) x 128(l) block tile, K-chunks of 16, register-staged double buffer.
// tf32 conversion happens ONCE per element at STS time; the compute loop is
// pure LDS + HMMA. Smem layout [m][k] pad 20 -> conflict-free fragment LDS.
// 8 warps in 2(m) x 4(n); warp tile 64x32 of m16n8k8 frags.
// ---------------------------------------------------------------------------
__global__ __launch_bounds__(256, 2) void gemm_qkv_tc(const float* __restrict__ W,
                                                      const float* __restrict__ x) {
    const int bb = blockIdx.z;
    const int om = blockIdx.y * 128;   // o tile
    const int ln = blockIdx.x * 128;   // l tile
    const float* X = x + (size_t)bb * L * D;
    float* C = g_qkv + (size_t)bb * OROWS * L;

    __shared__ alignas(16) uint32_t As[2][128][20];   // [buf][m][k]  (tf32 bits)
    __shared__ alignas(16) uint32_t Bs[2][128][20];   // [buf][n=l][k]

    const int tid  = threadIdx.x;
    const int warp = tid >> 5;
    const int lane = tid & 31;
    const int wm = warp >> 2;          // 0..1
    const int wn = warp & 3;           // 0..3
    const int grp = lane >> 2;         // 0..7
    const int qid = lane & 3;          // 0..3
    const int m0w = wm * 64;
    const int n0w = wn * 32;

    // loader mapping: 512 A-quads + 512 B-quads per chunk; thread does q=tid, tid+256
    const int r0q = tid >> 2;              // 0..63
    const int k0q = (tid & 3) * 4;         // 0,4,8,12
    const int r1q = r0q + 64;              // 64..127

    const float* wp0 = W + (size_t)(om + r0q) * D + k0q;
    const float* wp1 = W + (size_t)(om + r1q) * D + k0q;
    const float* xp0 = X + (size_t)(ln + r0q) * D + k0q;
    const float* xp1 = X + (size_t)(ln + r1q) * D + k0q;

    float acc[4][4][4];
#pragma unroll
    for (int i = 0; i < 4; i++)
#pragma unroll
        for (int j = 0; j < 4; j++)
#pragma unroll
            for (int r = 0; r < 4; r++) acc[i][j][r] = 0.f;

    float4 ra0, ra1, rb0, rb1;   // staging registers

    // prologue: LDG chunk 0
    ra0 = *(const float4*)(wp0);
    ra1 = *(const float4*)(wp1);
    rb0 = *(const float4*)(xp0);
    rb1 = *(const float4*)(xp1);

    const int NC = D / 16;  // 32 chunks
    for (int kc = 0; kc < NC; kc++) {
        const int buf = kc & 1;
        // convert + store current chunk
        *(uint4*)&As[buf][r0q][k0q] = tf4(ra0);
        *(uint4*)&As[buf][r1q][k0q] = tf4(ra1);
        *(uint4*)&Bs[buf][r0q][k0q] = tf4(rb0);
        *(uint4*)&Bs[buf][r1q][k0q] = tf4(rb1);
        __syncthreads();
        // issue next chunk's LDGs; latency hidden under compute
        if (kc + 1 < NC) {
            const int kg = (kc + 1) * 16;
            ra0 = *(const float4*)(wp0 + kg);
            ra1 = *(const float4*)(wp1 + kg);
            rb0 = *(const float4*)(xp0 + kg);
            rb1 = *(const float4*)(xp1 + kg);
        }

#pragma unroll
        for (int ks = 0; ks < 16; ks += 8) {
            uint32_t af[4][4];
#pragma unroll
            for (int mt = 0; mt < 4; mt++) {
                const int m = m0w + mt * 16 + grp;
                af[mt][0] = As[buf][m][ks + qid];
                af[mt][1] = As[buf][m + 8][ks + qid];
                af[mt][2] = As[buf][m][ks + qid + 4];
                af[mt][3] = As[buf][m + 8][ks + qid + 4];
            }
            uint32_t bf[4][2];
#pragma unroll
            for (int nt = 0; nt < 4; nt++) {
                const int n = n0w + nt * 8 + grp;
                bf[nt][0] = Bs[buf][n][ks + qid];
                bf[nt][1] = Bs[buf][n][ks + qid + 4];
            }
#pragma unroll
            for (int mt = 0; mt < 4; mt++)
#pragma unroll
                for (int nt = 0; nt < 4; nt++)
                    mma_tf32(acc[mt][nt], af[mt][0], af[mt][1], af[mt][2], af[mt][3],
                             bf[nt][0], bf[nt][1]);
        }
        // no second sync needed: next iteration's STS targets the other buffer,
        // and the per-iter barrier bounds warp skew to <1 iteration.
    }

    // epilogue: C[m=o][n=l]
#pragma unroll
    for (int mt = 0; mt < 4; mt++) {
        const int ro = om + m0w + mt * 16 + grp;
#pragma unroll
        for (int nt = 0; nt < 4; nt++) {
            const int cl = ln + n0w + nt * 8 + qid * 2;
            *(float2*)(C + (size_t)ro * L + cl) =
                make_float2(acc[mt][nt][0], acc[mt][nt][1]);
            *(float2*)(C + (size_t)(ro + 8) * L + cl) =
                make_float2(acc[mt][nt][2], acc[mt][nt][3]);
        }
    }
}

// ---------------------------------------------------------------------------
// Kernel 2: softmax over L on k rows (rows 512..1023 per batch), contiguous.
// ---------------------------------------------------------------------------
__global__ __launch_bounds__(256) void softmax_k() {
    const int r = blockIdx.x;           // 0..511
    const int bb = blockIdx.y;
    float* row = g_qkv + ((size_t)bb * OROWS + 512 + r) * L;
    const int tid = threadIdx.x;

    float4 v[4];
    float mx = -1e30f;
#pragma unroll
    for (int i = 0; i < 4; i++) {
        v[i] = *(float4*)(row + (size_t)(i * 256 + tid) * 4);
        mx = fmaxf(mx, fmaxf(fmaxf(v[i].x, v[i].y), fmaxf(v[i].z, v[i].w)));
    }
    __shared__ float redm[8];
    __shared__ float reds[8];
#pragma unroll
    for (int off = 16; off; off >>= 1)
        mx = fmaxf(mx, __shfl_xor_sync(0xffffffffu, mx, off));
    if ((tid & 31) == 0) redm[tid >> 5] = mx;
    __syncthreads();
    mx = redm[0];
#pragma unroll
    for (int i = 1; i < 8; i++) mx = fmaxf(mx, redm[i]);

    float s = 0.f;
#pragma unroll
    for (int i = 0; i < 4; i++) {
        v[i].x = __expf(v[i].x - mx); v[i].y = __expf(v[i].y - mx);
        v[i].z = __expf(v[i].z - mx); v[i].w = __expf(v[i].w - mx);
        s += v[i].x + v[i].y + v[i].z + v[i].w;
    }
#pragma unroll
    for (int off = 16; off; off >>= 1)
        s += __shfl_xor_sync(0xffffffffu, s, off);
    if ((tid & 31) == 0) reds[tid >> 5] = s;
    __syncthreads();
    s = reds[0];
#pragma unroll
    for (int i = 1; i < 8; i++) s += reds[i];
    const float inv = 1.f / s;
#pragma unroll
    for (int i = 0; i < 4; i++) {
        v[i].x *= inv; v[i].y *= inv; v[i].z *= inv; v[i].w *= inv;
        *(float4*)(row + (size_t)(i * 256 + tid) * 4) = v[i];
    }
}

// ---------------------------------------------------------------------------
// Kernel 3: softmax over C (64) on q, per (b,h,l).
// ---------------------------------------------------------------------------
__global__ __launch_bounds__(256) void softmax_q() {
    const int l = blockIdx.x * 256 + threadIdx.x;
    const int h = blockIdx.y;
    const int bb = blockIdx.z;
    float* base = g_qkv + ((size_t)bb * OROWS + h * CH) * L + l;

    float vals[64];
    float mx = -1e30f;
#pragma unroll
    for (int c = 0; c < 64; c++) {
        vals[c] = base[(size_t)c * L];
        mx = fmaxf(mx, vals[c]);
    }
    float s = 0.f;
#pragma unroll
    for (int c = 0; c < 64; c++) {
        vals[c] = __expf(vals[c] - mx);
        s += vals[c];
    }
    const float inv = 1.f / s;
#pragma unroll
    for (int c = 0; c < 64; c++)
        base[(size_t)c * L] = vals[c] * inv;
}

// ---------------------------------------------------------------------------
// Kernel 4a: zero ctx accumulator
// ---------------------------------------------------------------------------
__global__ void zero_ctx() {
    g_ctx[blockIdx.x * 256 + threadIdx.x] = 0.f;
}

// ---------------------------------------------------------------------------
// Kernel 4: ctx[b,h,d,e] = sum_n k[b,h,d,n] * v[b,h,e,n]   (fp32 FFMA, small)
// ---------------------------------------------------------------------------
__global__ __launch_bounds__(256) void ctx_kernel() {
    const int bh = blockIdx.x;          // 0..63
    const int bb = bh >> 3, h = bh & 7;
    const int n_start = blockIdx.y * 512;
    const float* kp = g_qkv + ((size_t)bb * OROWS + 512  + h * CH) * L;
    const float* vp = g_qkv + ((size_t)bb * OROWS + 1024 + h * CH) * L;

    __shared__ float ks[64][65];
    __shared__ float vs[64][65];
    const int tid = threadIdx.x;
    const int tx = tid & 15, ty = tid >> 4;

    float acc[4][4];
#pragma unroll
    for (int i = 0; i < 4; i++)
#pragma unroll
        for (int j = 0; j < 4; j++) acc[i][j] = 0.f;

    for (int n0 = n_start; n0 < n_start + 512; n0 += 64) {
        for (int idx = tid; idx < 1024; idx += 256) {
            const int row = idx >> 4, c4 = (idx & 15) * 4;
            float4 kk = *(const float4*)(kp + (size_t)row * L + n0 + c4);
            ks[row][c4] = kk.x; ks[row][c4 + 1] = kk.y;
            ks[row][c4 + 2] = kk.z; ks[row][c4 + 3] = kk.w;
            float4 vv = *(const float4*)(vp + (size_t)row * L + n0 + c4);
            vs[row][c4] = vv.x; vs[row][c4 + 1] = vv.y;
            vs[row][c4 + 2] = vv.z; vs[row][c4 + 3] = vv.w;
        }
        __syncthreads();
#pragma unroll 16
        for (int n = 0; n < 64; n++) {
            float ar[4], br[4];
#pragma unroll
            for (int i = 0; i < 4; i++) ar[i] = ks[ty * 4 + i][n];
#pragma unroll
            for (int j = 0; j < 4; j++) br[j] = vs[tx * 4 + j][n];
#pragma unroll
            for (int i = 0; i < 4; i++)
#pragma unroll
                for (int j = 0; j < 4; j++)
                    acc[i][j] += ar[i] * br[j];
        }
        __syncthreads();
    }
    float* cbase = g_ctx + (size_t)bh * CH * CH;
#pragma unroll
    for (int i = 0; i < 4; i++)
#pragma unroll
        for (int j = 0; j < 4; j++)
            atomicAdd(&cbase[(ty * 4 + i) * CH + tx * 4 + j], acc[i][j]);
}

// ---------------------------------------------------------------------------
// Kernel 5: fold ctx into Wout:
//   A[b, h*64+d, dout] = sum_e ctx[b,h,d,e] * Wout[dout, h*64+e]   (fp32, small)
// ---------------------------------------------------------------------------
__global__ __launch_bounds__(256) void a_kernel(const float* __restrict__ Wout) {
    const int bh = blockIdx.x;
    const int bb = bh >> 3, h = bh & 7;
    const int d0 = blockIdx.y * 64;     // dout tile
    const float* ctx = g_ctx + (size_t)bh * CH * CH;

    __shared__ float cs[64][65];
    __shared__ float ws[64][65];
    const int tid = threadIdx.x;
    const int tx = tid & 15, ty = tid >> 4;

    for (int idx = tid; idx < 1024; idx += 256) {
        const int row = idx >> 4, e4 = (idx & 15) * 4;
        float4 c4 = *(const float4*)(ctx + row * CH + e4);
        cs[row][e4] = c4.x; cs[row][e4 + 1] = c4.y;
        cs[row][e4 + 2] = c4.z; cs[row][e4 + 3] = c4.w;
        float4 w4 = *(const float4*)(Wout + (size_t)(d0 + row) * D + h * CH + e4);
        ws[row][e4] = w4.x; ws[row][e4 + 1] = w4.y;
        ws[row][e4 + 2] = w4.z; ws[row][e4 + 3] = w4.w;
    }
    __syncthreads();

    float acc[4][4];
#pragma unroll
    for (int i = 0; i < 4; i++)
#pragma unroll
        for (int j = 0; j < 4; j++) acc[i][j] = 0.f;

#pragma unroll 16
    for (int e = 0; e < 64; e++) {
        float ar[4], br[4];
#pragma unroll
        for (int i = 0; i < 4; i++) ar[i] = cs[ty * 4 + i][e];
#pragma unroll
        for (int j = 0; j < 4; j++) br[j] = ws[tx * 4 + j][e];
#pragma unroll
        for (int i = 0; i < 4; i++)
#pragma unroll
            for (int j = 0; j < 4; j++)
                acc[i][j] += ar[i] * br[j];
    }
    float* Ab = g_A + (size_t)bb * D * D;
#pragma unroll
    for (int i = 0; i < 4; i++)
#pragma unroll
        for (int j = 0; j < 4; j++)
            Ab[(size_t)(h * CH + ty * 4 + i) * D + d0 + tx * 4 + j] = acc[i][j];
}

// ---------------------------------------------------------------------------
// Kernel 6 (tf32 TC): y[b,l,d] = sum_c q_sm[b,c,l] * A[b,c,d] + bout[d]
// Both operands K-outer in gmem -> rows copy directly into [k][mn] smem
// (pad 136 -> conflict-free fragment LDS). Register-staged double buffer,
// tf32 conversion once per element at STS time.
// ---------------------------------------------------------------------------
__global__ __launch_bounds__(256, 2) void gemm_out_tc(const float* __restrict__ bout,
                                                      float* __restrict__ y) {
    const int bb = blockIdx.z;
    const int l0 = blockIdx.x * 128;
    const int d0 = blockIdx.y * 128;
    const float* Q  = g_qkv + (size_t)bb * OROWS * L;   // q rows 0..511: [c][l]
    const float* Ab = g_A   + (size_t)bb * D * D;       // [c][d]

    __shared__ alignas(16) uint32_t As[2][16][136];   // [buf][k][m=l]  (tf32 bits)
    __shared__ alignas(16) uint32_t Bs[2][16][136];   // [buf][k][n=d]

    const int tid  = threadIdx.x;
    const int warp = tid >> 5;
    const int lane = tid & 31;
    const int wm = warp >> 2;          // 0..1
    const int wn = warp & 3;           // 0..3
    const int grp = lane >> 2;
    const int qid = lane & 3;
    const int m0w = wm * 64;
    const int n0w = wn * 32;

    // loader: 16 rows x 32 quads per operand per chunk; thread does kr0, kr0+8
    const int kr0 = tid >> 5;                // 0..7
    const int mq  = (tid & 31) * 4;          // 0..124
    const int kr1 = kr0 + 8;                 // 8..15

    const float* qp0 = Q  + (size_t)kr0 * L + l0 + mq;
    const float* qp1 = Q  + (size_t)kr1 * L + l0 + mq;
    const float* ap0 = Ab + (size_t)kr0 * D + d0 + mq;
    const float* ap1 = Ab + (size_t)kr1 * D + d0 + mq;

    float acc[4][4][4];
#pragma unroll
    for (int i = 0; i < 4; i++)
#pragma unroll
        for (int j = 0; j < 4; j++)
#pragma unroll
            for (int r = 0; r < 4; r++) acc[i][j][r] = 0.f;

    float4 ra0, ra1, rb0, rb1;
    ra0 = *(const float4*)(qp0);
    ra1 = *(const float4*)(qp1);
    rb0 = *(const float4*)(ap0);
    rb1 = *(const float4*)(ap1);

    const int NC = D / 16;  // 32
    for (int kc = 0; kc < NC; kc++) {
        const int buf = kc & 1;
        *(uint4*)&As[buf][kr0][mq] = tf4(ra0);
        *(uint4*)&As[buf][kr1][mq] = tf4(ra1);
        *(uint4*)&Bs[buf][kr0][mq] = tf4(rb0);
        *(uint4*)&Bs[buf][kr1][mq] = tf4(rb1);
        __syncthreads();
        if (kc + 1 < NC) {
            const size_t kgl = (size_t)(kc + 1) * 16 * L;
            const size_t kgd = (size_t)(kc + 1) * 16 * D;
            ra0 = *(const float4*)(qp0 + kgl);
            ra1 = *(const float4*)(qp1 + kgl);
            rb0 = *(const float4*)(ap0 + kgd);
            rb1 = *(const float4*)(ap1 + kgd);
        }

#pragma unroll
        for (int ks = 0; ks < 16; ks += 8) {
            uint32_t af[4][4];
#pragma unroll
            for (int mt = 0; mt < 4; mt++) {
                const int m = m0w + mt * 16 + grp;
                af[mt][0] = As[buf][ks + qid][m];
                af[mt][1] = As[buf][ks + qid][m + 8];
                af[mt][2] = As[buf][ks + qid + 4][m];
                af[mt][3] = As[buf][ks + qid + 4][m + 8];
            }
            uint32_t bf[4][2];
#pragma unroll
            for (int nt = 0; nt < 4; nt++) {
                const int n = n0w + nt * 8 + grp;
                bf[nt][0] = Bs[buf][ks + qid][n];
                bf[nt][1] = Bs[buf][ks + qid + 4][n];
            }
#pragma unroll
            for (int mt = 0; mt < 4; mt++)
#pragma unroll
                for (int nt = 0; nt < 4; nt++)
                    mma_tf32(acc[mt][nt], af[mt][0], af[mt][1], af[mt][2], af[mt][3],
                             bf[nt][0], bf[nt][1]);
        }
    }

    // epilogue: y[l][d] + bias
    float* Y = y + (size_t)bb * L * D;
#pragma unroll
    for (int nt = 0; nt < 4; nt++) {
        const int col = d0 + n0w + nt * 8 + qid * 2;
        const float b0v = __ldg(bout + col);
        const float b1v = __ldg(bout + col + 1);
#pragma unroll
        for (int mt = 0; mt < 4; mt++) {
            const int rl = l0 + m0w + mt * 16 + grp;
            *(float2*)(Y + (size_t)rl * D + col) =
                make_float2(acc[mt][nt][0] + b0v, acc[mt][nt][1] + b1v);
            *(float2*)(Y + (size_t)(rl + 8) * D + col) =
                make_float2(acc[mt][nt][2] + b0v, acc[mt][nt][3] + b1v);
        }
    }
}

// ---------------------------------------------------------------------------
extern "C" void kernel_launch(void* const* d_in, const int* in_sizes, int n_in,
                              void* d_out, int out_size) {
    const float* x    = (const float*)d_in[0];   // [8,4096,512]
    const float* Wqkv = (const float*)d_in[1];   // [1536,512]
    const float* Wout = (const float*)d_in[2];   // [512,512]
    const float* bout = (const float*)d_in[3];   // [512]
    float* y = (float*)d_out;                    // [8,4096,512]

    gemm_qkv_tc<<<dim3(L / 128, OROWS / 128, NB), 256>>>(Wqkv, x);
    softmax_k<<<dim3(512, NB), 256>>>();
    softmax_q<<<dim3(L / 256, NHEADS, NB), 256>>>();
    zero_ctx<<<(NB * NHEADS * CH * CH) / 256, 256>>>();
    ctx_kernel<<<dim3(NB * NHEADS, 8), 256>>>();
    a_kernel<<<dim3(NB * NHEADS, D / 64), 256>>>(Wout);
    gemm_out_tc<<<dim3(L / 128, D / 128, NB), 256>>>(bout, y);
}

// round 12
// speedup vs baseline: 1.5921x; 1.5921x over previous
#include <cuda_runtime.h>
#include <cstdint>

#define L 4096
#define D 512
#define NHEADS 8
#define CH 64
#define NB 8
#define OROWS 1536   // 3 * NHEADS * CH

// Scratch (device globals: no allocation allowed)
__device__ float    g_qkv[(size_t)NB * OROWS * L];   // [B][1536][L]; q rows 0..511 become tf32 bits after softmax_q
__device__ float    g_ctx[NB * NHEADS * CH * CH];    // [B][H][64][64]
__device__ uint32_t g_A[NB * D * D];                 // [B][512 c][512 d]  tf32 bits
__device__ uint32_t g_xtf[(size_t)NB * L * D];       // x converted to tf32 bits
__device__ uint32_t g_wtf[OROWS * D];                // Wqkv converted to tf32 bits

// ---------------------------------------------------------------------------
// tf32 tensor-core helpers
// ---------------------------------------------------------------------------
__device__ __forceinline__ uint32_t f2tf(float x) {
    uint32_t r;
    asm("cvt.rna.tf32.f32 %0, %1;" : "=r"(r) : "f"(x));
    return r;
}

__device__ __forceinline__ uint4 tf4(float4 v) {
    return make_uint4(f2tf(v.x), f2tf(v.y), f2tf(v.z), f2tf(v.w));
}

__device__ __forceinline__ void mma_tf32(float* c,
                                         uint32_t a0, uint32_t a1, uint32_t a2, uint32_t a3,
                                         uint32_t b0, uint32_t b1) {
    asm volatile(
        "mma.sync.aligned.m16n8k8.row.col.f32.tf32.tf32.f32 "
        "{%0,%1,%2,%3}, {%4,%5,%6,%7}, {%8,%9}, {%0,%1,%2,%3};"
        : "+f"(c[0]), "+f"(c[1]), "+f"(c[2]), "+f"(c[3])
        : "r"(a0), "r"(a1), "r"(a2), "r"(a3), "r"(b0), "r"(b1));
}

__device__ __forceinline__ void cp_async16(void* smem, const void* gmem) {
    uint32_t s = (uint32_t)__cvta_generic_to_shared(smem);
    asm volatile("cp.async.ca.shared.global [%0], [%1], 16;\n" :: "r"(s), "l"(gmem));
}
#define CP_COMMIT() asm volatile("cp.async.commit_group;\n" ::: "memory")
#define CP_WAIT(n)  asm volatile("cp.async.wait_group %0;\n" :: "n"(n) : "memory")

// ---------------------------------------------------------------------------
// Kernel 0: elementwise fp32 -> tf32-bits conversion (vectorized), n = quads
// ---------------------------------------------------------------------------
__global__ __launch_bounds__(256) void convert_tf32(const float* __restrict__ src,
                                                    uint32_t* __restrict__ dst) {
    const size_t idx = (size_t)blockIdx.x * 256 + threadIdx.x;
    ((uint4*)dst)[idx] = tf4(((const float4*)src)[idx]);
}

// ---------------------------------------------------------------------------
// Kernel 1 (tf32 TC): qkv[b,o,l] = sum_d Wqkv[o,d] * x[b,l,d]
// Inputs are pre-converted tf32 bits -> mainloop is pure cp.async + LDS + HMMA.
// 128(o) x 128(l) block tile, K-chunks of 16, cp.async double buffered.
// Smem layout [m][k] pad 20 -> conflict-free fragment LDS.
// 8 warps in 2(m) x 4(n); warp tile 64x32 of m16n8k8 frags.
// ---------------------------------------------------------------------------
__global__ __launch_bounds__(256, 2) void gemm_qkv_tc(const uint32_t* __restrict__ W,
                                                      const uint32_t* __restrict__ Xall) {
    const int bb = blockIdx.z;
    const int om = blockIdx.y * 128;   // o tile
    const int ln = blockIdx.x * 128;   // l tile
    const uint32_t* X = Xall + (size_t)bb * L * D;
    float* C = g_qkv + (size_t)bb * OROWS * L;

    __shared__ alignas(16) uint32_t As[2][128][20];   // [buf][m][k]
    __shared__ alignas(16) uint32_t Bs[2][128][20];   // [buf][n=l][k]

    const int tid  = threadIdx.x;
    const int warp = tid >> 5;
    const int lane = tid & 31;
    const int wm = warp >> 2;          // 0..1
    const int wn = warp & 3;           // 0..3
    const int grp = lane >> 2;         // 0..7
    const int qid = lane & 3;          // 0..3
    const int m0w = wm * 64;
    const int n0w = wn * 32;

    // loader mapping: 512 A-quads + 512 B-quads per chunk; thread does q=tid, tid+256
    const int r0q = tid >> 2;              // 0..63
    const int k0q = (tid & 3) * 4;         // 0,4,8,12
    const int r1q = r0q + 64;              // 64..127

    float acc[4][4][4];
#pragma unroll
    for (int i = 0; i < 4; i++)
#pragma unroll
        for (int j = 0; j < 4; j++)
#pragma unroll
            for (int r = 0; r < 4; r++) acc[i][j][r] = 0.f;

    // prologue: chunk 0 -> buf 0
    {
        cp_async16(&As[0][r0q][k0q], W + (size_t)(om + r0q) * D + k0q);
        cp_async16(&As[0][r1q][k0q], W + (size_t)(om + r1q) * D + k0q);
        cp_async16(&Bs[0][r0q][k0q], X + (size_t)(ln + r0q) * D + k0q);
        cp_async16(&Bs[0][r1q][k0q], X + (size_t)(ln + r1q) * D + k0q);
        CP_COMMIT();
    }

    const int NC = D / 16;  // 32 chunks
    for (int kc = 0; kc < NC; kc++) {
        const int buf = kc & 1;
        if (kc + 1 < NC) {
            const int nb = buf ^ 1;
            const int kg = (kc + 1) * 16 + k0q;
            cp_async16(&As[nb][r0q][k0q], W + (size_t)(om + r0q) * D + kg);
            cp_async16(&As[nb][r1q][k0q], W + (size_t)(om + r1q) * D + kg);
            cp_async16(&Bs[nb][r0q][k0q], X + (size_t)(ln + r0q) * D + kg);
            cp_async16(&Bs[nb][r1q][k0q], X + (size_t)(ln + r1q) * D + kg);
            CP_COMMIT();
            CP_WAIT(1);
        } else {
            CP_WAIT(0);
        }
        __syncthreads();

#pragma unroll
        for (int ks = 0; ks < 16; ks += 8) {
            uint32_t af[4][4];
#pragma unroll
            for (int mt = 0; mt < 4; mt++) {
                const int m = m0w + mt * 16 + grp;
                af[mt][0] = As[buf][m][ks + qid];
                af[mt][1] = As[buf][m + 8][ks + qid];
                af[mt][2] = As[buf][m][ks + qid + 4];
                af[mt][3] = As[buf][m + 8][ks + qid + 4];
            }
            uint32_t bf[4][2];
#pragma unroll
            for (int nt = 0; nt < 4; nt++) {
                const int n = n0w + nt * 8 + grp;
                bf[nt][0] = Bs[buf][n][ks + qid];
                bf[nt][1] = Bs[buf][n][ks + qid + 4];
            }
#pragma unroll
            for (int mt = 0; mt < 4; mt++)
#pragma unroll
                for (int nt = 0; nt < 4; nt++)
                    mma_tf32(acc[mt][nt], af[mt][0], af[mt][1], af[mt][2], af[mt][3],
                             bf[nt][0], bf[nt][1]);
        }
        __syncthreads();
    }

    // epilogue: C[m=o][n=l]  (fp32)
#pragma unroll
    for (int mt = 0; mt < 4; mt++) {
        const int ro = om + m0w + mt * 16 + grp;
#pragma unroll
        for (int nt = 0; nt < 4; nt++) {
            const int cl = ln + n0w + nt * 8 + qid * 2;
            *(float2*)(C + (size_t)ro * L + cl) =
                make_float2(acc[mt][nt][0], acc[mt][nt][1]);
            *(float2*)(C + (size_t)(ro + 8) * L + cl) =
                make_float2(acc[mt][nt][2], acc[mt][nt][3]);
        }
    }
}

// ---------------------------------------------------------------------------
// Kernel 2: softmax over L on k rows (rows 512..1023 per batch), contiguous.
// ---------------------------------------------------------------------------
__global__ __launch_bounds__(256) void softmax_k() {
    const int r = blockIdx.x;           // 0..511
    const int bb = blockIdx.y;
    float* row = g_qkv + ((size_t)bb * OROWS + 512 + r) * L;
    const int tid = threadIdx.x;

    float4 v[4];
    float mx = -1e30f;
#pragma unroll
    for (int i = 0; i < 4; i++) {
        v[i] = *(float4*)(row + (size_t)(i * 256 + tid) * 4);
        mx = fmaxf(mx, fmaxf(fmaxf(v[i].x, v[i].y), fmaxf(v[i].z, v[i].w)));
    }
    __shared__ float redm[8];
    __shared__ float reds[8];
#pragma unroll
    for (int off = 16; off; off >>= 1)
        mx = fmaxf(mx, __shfl_xor_sync(0xffffffffu, mx, off));
    if ((tid & 31) == 0) redm[tid >> 5] = mx;
    __syncthreads();
    mx = redm[0];
#pragma unroll
    for (int i = 1; i < 8; i++) mx = fmaxf(mx, redm[i]);

    float s = 0.f;
#pragma unroll
    for (int i = 0; i < 4; i++) {
        v[i].x = __expf(v[i].x - mx); v[i].y = __expf(v[i].y - mx);
        v[i].z = __expf(v[i].z - mx); v[i].w = __expf(v[i].w - mx);
        s += v[i].x + v[i].y + v[i].z + v[i].w;
    }
#pragma unroll
    for (int off = 16; off; off >>= 1)
        s += __shfl_xor_sync(0xffffffffu, s, off);
    if ((tid & 31) == 0) reds[tid >> 5] = s;
    __syncthreads();
    s = reds[0];
#pragma unroll
    for (int i = 1; i < 8; i++) s += reds[i];
    const float inv = 1.f / s;
#pragma unroll
    for (int i = 0; i < 4; i++) {
        v[i].x *= inv; v[i].y *= inv; v[i].z *= inv; v[i].w *= inv;
        *(float4*)(row + (size_t)(i * 256 + tid) * 4) = v[i];
    }
}

// ---------------------------------------------------------------------------
// Kernel 3: softmax over C (64) on q, per (b,h,l). Writes tf32 BITS in place
// (q region is only consumed by the tf32 gemm_out afterwards).
// ---------------------------------------------------------------------------
__global__ __launch_bounds__(256) void softmax_q() {
    const int l = blockIdx.x * 256 + threadIdx.x;
    const int h = blockIdx.y;
    const int bb = blockIdx.z;
    float* base = g_qkv + ((size_t)bb * OROWS + h * CH) * L + l;
    uint32_t* baseu = (uint32_t*)base;

    float vals[64];
    float mx = -1e30f;
#pragma unroll
    for (int c = 0; c < 64; c++) {
        vals[c] = base[(size_t)c * L];
        mx = fmaxf(mx, vals[c]);
    }
    float s = 0.f;
#pragma unroll
    for (int c = 0; c < 64; c++) {
        vals[c] = __expf(vals[c] - mx);
        s += vals[c];
    }
    const float inv = 1.f / s;
#pragma unroll
    for (int c = 0; c < 64; c++)
        baseu[(size_t)c * L] = f2tf(vals[c] * inv);
}

// ---------------------------------------------------------------------------
// Kernel 4a: zero ctx accumulator
// ---------------------------------------------------------------------------
__global__ void zero_ctx() {
    g_ctx[blockIdx.x * 256 + threadIdx.x] = 0.f;
}

// ---------------------------------------------------------------------------
// Kernel 4: ctx[b,h,d,e] = sum_n k[b,h,d,n] * v[b,h,e,n]   (fp32 FFMA, small)
// ---------------------------------------------------------------------------
__global__ __launch_bounds__(256) void ctx_kernel() {
    const int bh = blockIdx.x;          // 0..63
    const int bb = bh >> 3, h = bh & 7;
    const int n_start = blockIdx.y * 512;
    const float* kp = g_qkv + ((size_t)bb * OROWS + 512  + h * CH) * L;
    const float* vp = g_qkv + ((size_t)bb * OROWS + 1024 + h * CH) * L;

    __shared__ float ks[64][65];
    __shared__ float vs[64][65];
    const int tid = threadIdx.x;
    const int tx = tid & 15, ty = tid >> 4;

    float acc[4][4];
#pragma unroll
    for (int i = 0; i < 4; i++)
#pragma unroll
        for (int j = 0; j < 4; j++) acc[i][j] = 0.f;

    for (int n0 = n_start; n0 < n_start + 512; n0 += 64) {
        for (int idx = tid; idx < 1024; idx += 256) {
            const int row = idx >> 4, c4 = (idx & 15) * 4;
            float4 kk = *(const float4*)(kp + (size_t)row * L + n0 + c4);
            ks[row][c4] = kk.x; ks[row][c4 + 1] = kk.y;
            ks[row][c4 + 2] = kk.z; ks[row][c4 + 3] = kk.w;
            float4 vv = *(const float4*)(vp + (size_t)row * L + n0 + c4);
            vs[row][c4] = vv.x; vs[row][c4 + 1] = vv.y;
            vs[row][c4 + 2] = vv.z; vs[row][c4 + 3] = vv.w;
        }
        __syncthreads();
#pragma unroll 16
        for (int n = 0; n < 64; n++) {
            float ar[4], br[4];
#pragma unroll
            for (int i = 0; i < 4; i++) ar[i] = ks[ty * 4 + i][n];
#pragma unroll
            for (int j = 0; j < 4; j++) br[j] = vs[tx * 4 + j][n];
#pragma unroll
            for (int i = 0; i < 4; i++)
#pragma unroll
                for (int j = 0; j < 4; j++)
                    acc[i][j] += ar[i] * br[j];
        }
        __syncthreads();
    }
    float* cbase = g_ctx + (size_t)bh * CH * CH;
#pragma unroll
    for (int i = 0; i < 4; i++)
#pragma unroll
        for (int j = 0; j < 4; j++)
            atomicAdd(&cbase[(ty * 4 + i) * CH + tx * 4 + j], acc[i][j]);
}

// ---------------------------------------------------------------------------
// Kernel 5: fold ctx into Wout, store A as tf32 BITS:
//   A[b, h*64+d, dout] = sum_e ctx[b,h,d,e] * Wout[dout, h*64+e]
// ---------------------------------------------------------------------------
__global__ __launch_bounds__(256) void a_kernel(const float* __restrict__ Wout) {
    const int bh = blockIdx.x;
    const int bb = bh >> 3, h = bh & 7;
    const int d0 = blockIdx.y * 64;     // dout tile
    const float* ctx = g_ctx + (size_t)bh * CH * CH;

    __shared__ float cs[64][65];
    __shared__ float ws[64][65];
    const int tid = threadIdx.x;
    const int tx = tid & 15, ty = tid >> 4;

    for (int idx = tid; idx < 1024; idx += 256) {
        const int row = idx >> 4, e4 = (idx & 15) * 4;
        float4 c4 = *(const float4*)(ctx + row * CH + e4);
        cs[row][e4] = c4.x; cs[row][e4 + 1] = c4.y;
        cs[row][e4 + 2] = c4.z; cs[row][e4 + 3] = c4.w;
        float4 w4 = *(const float4*)(Wout + (size_t)(d0 + row) * D + h * CH + e4);
        ws[row][e4] = w4.x; ws[row][e4 + 1] = w4.y;
        ws[row][e4 + 2] = w4.z; ws[row][e4 + 3] = w4.w;
    }
    __syncthreads();

    float acc[4][4];
#pragma unroll
    for (int i = 0; i < 4; i++)
#pragma unroll
        for (int j = 0; j < 4; j++) acc[i][j] = 0.f;

#pragma unroll 16
    for (int e = 0; e < 64; e++) {
        float ar[4], br[4];
#pragma unroll
        for (int i = 0; i < 4; i++) ar[i] = cs[ty * 4 + i][e];
#pragma unroll
        for (int j = 0; j < 4; j++) br[j] = ws[tx * 4 + j][e];
#pragma unroll
        for (int i = 0; i < 4; i++)
#pragma unroll
            for (int j = 0; j < 4; j++)
                acc[i][j] += ar[i] * br[j];
    }
    uint32_t* Ab = g_A + (size_t)bb * D * D;
#pragma unroll
    for (int i = 0; i < 4; i++)
#pragma unroll
        for (int j = 0; j < 4; j++)
            Ab[(size_t)(h * CH + ty * 4 + i) * D + d0 + tx * 4 + j] = f2tf(acc[i][j]);
}

// ---------------------------------------------------------------------------
// Kernel 6 (tf32 TC): y[b,l,d] = sum_c q_sm[b,c,l] * A[b,c,d] + bout[d]
// Both operands are pre-converted tf32 bits, K-outer in gmem -> cp.async rows
// directly into [k][mn] smem (pad 136 -> conflict-free fragment LDS).
// 128(l) x 128(d), K chunks of 16, double buffered. Pure LDS + HMMA loop.
// ---------------------------------------------------------------------------
__global__ __launch_bounds__(256, 2) void gemm_out_tc(const float* __restrict__ bout,
                                                      float* __restrict__ y) {
    const int bb = blockIdx.z;
    const int l0 = blockIdx.x * 128;
    const int d0 = blockIdx.y * 128;
    const uint32_t* Q  = (const uint32_t*)(g_qkv + (size_t)bb * OROWS * L); // q rows 0..511: [c][l] tf32 bits
    const uint32_t* Ab = g_A + (size_t)bb * D * D;                          // [c][d] tf32 bits

    __shared__ alignas(16) uint32_t As[2][16][136];   // [buf][k][m=l]
    __shared__ alignas(16) uint32_t Bs[2][16][136];   // [buf][k][n=d]

    const int tid  = threadIdx.x;
    const int warp = tid >> 5;
    const int lane = tid & 31;
    const int wm = warp >> 2;          // 0..1
    const int wn = warp & 3;           // 0..3
    const int grp = lane >> 2;
    const int qid = lane & 3;
    const int m0w = wm * 64;
    const int n0w = wn * 32;

    // loader: 512 quads per operand per chunk (16 rows x 32 quads); q = tid, tid+256
    const int kr0 = tid >> 5;                // 0..7
    const int mq  = (tid & 31) * 4;          // 0..124
    const int kr1 = kr0 + 8;                 // 8..15

    float acc[4][4][4];
#pragma unroll
    for (int i = 0; i < 4; i++)
#pragma unroll
        for (int j = 0; j < 4; j++)
#pragma unroll
            for (int r = 0; r < 4; r++) acc[i][j][r] = 0.f;

    {
        cp_async16(&As[0][kr0][mq], Q  + (size_t)kr0 * L + l0 + mq);
        cp_async16(&As[0][kr1][mq], Q  + (size_t)kr1 * L + l0 + mq);
        cp_async16(&Bs[0][kr0][mq], Ab + (size_t)kr0 * D + d0 + mq);
        cp_async16(&Bs[0][kr1][mq], Ab + (size_t)kr1 * D + d0 + mq);
        CP_COMMIT();
    }

    const int NC = D / 16;  // 32
    for (int kc = 0; kc < NC; kc++) {
        const int buf = kc & 1;
        if (kc + 1 < NC) {
            const int nb = buf ^ 1;
            const int kg = (kc + 1) * 16;
            cp_async16(&As[nb][kr0][mq], Q  + (size_t)(kg + kr0) * L + l0 + mq);
            cp_async16(&As[nb][kr1][mq], Q  + (size_t)(kg + kr1) * L + l0 + mq);
            cp_async16(&Bs[nb][kr0][mq], Ab + (size_t)(kg + kr0) * D + d0 + mq);
            cp_async16(&Bs[nb][kr1][mq], Ab + (size_t)(kg + kr1) * D + d0 + mq);
            CP_COMMIT();
            CP_WAIT(1);
        } else {
            CP_WAIT(0);
        }
        __syncthreads();

#pragma unroll
        for (int ks = 0; ks < 16; ks += 8) {
            uint32_t af[4][4];
#pragma unroll
            for (int mt = 0; mt < 4; mt++) {
                const int m = m0w + mt * 16 + grp;
                af[mt][0] = As[buf][ks + qid][m];
                af[mt][1] = As[buf][ks + qid][m + 8];
                af[mt][2] = As[buf][ks + qid + 4][m];
                af[mt][3] = As[buf][ks + qid + 4][m + 8];
            }
            uint32_t bf[4][2];
#pragma unroll
            for (int nt = 0; nt < 4; nt++) {
                const int n = n0w + nt * 8 + grp;
                bf[nt][0] = Bs[buf][ks + qid][n];
                bf[nt][1] = Bs[buf][ks + qid + 4][n];
            }
#pragma unroll
            for (int mt = 0; mt < 4; mt++)
#pragma unroll
                for (int nt = 0; nt < 4; nt++)
                    mma_tf32(acc[mt][nt], af[mt][0], af[mt][1], af[mt][2], af[mt][3],
                             bf[nt][0], bf[nt][1]);
        }
        __syncthreads();
    }

    // epilogue: y[l][d] + bias
    float* Y = y + (size_t)bb * L * D;
#pragma unroll
    for (int nt = 0; nt < 4; nt++) {
        const int col = d0 + n0w + nt * 8 + qid * 2;
        const float b0v = __ldg(bout + col);
        const float b1v = __ldg(bout + col + 1);
#pragma unroll
        for (int mt = 0; mt < 4; mt++) {
            const int rl = l0 + m0w + mt * 16 + grp;
            *(float2*)(Y + (size_t)rl * D + col) =
                make_float2(acc[mt][nt][0] + b0v, acc[mt][nt][1] + b1v);
            *(float2*)(Y + (size_t)(rl + 8) * D + col) =
                make_float2(acc[mt][nt][2] + b0v, acc[mt][nt][3] + b1v);
        }
    }
}

// ---------------------------------------------------------------------------
extern "C" void kernel_launch(void* const* d_in, const int* in_sizes, int n_in,
                              void* d_out, int out_size) {
    const float* x    = (const float*)d_in[0];   // [8,4096,512]
    const float* Wqkv = (const float*)d_in[1];   // [1536,512]
    const float* Wout = (const float*)d_in[2];   // [512,512]
    const float* bout = (const float*)d_in[3];   // [512]
    float* y = (float*)d_out;                    // [8,4096,512]

    uint32_t* xtf;  cudaGetSymbolAddress((void**)&xtf, g_xtf);
    uint32_t* wtf;  cudaGetSymbolAddress((void**)&wtf, g_wtf);

    // pre-convert inputs to tf32 bits (elementwise, bandwidth-bound)
    convert_tf32<<<(NB * L * D / 4) / 256, 256>>>(x, xtf);
    convert_tf32<<<(OROWS * D / 4) / 256, 256>>>(Wqkv, wtf);

    gemm_qkv_tc<<<dim3(L / 128, OROWS / 128, NB), 256>>>(wtf, xtf);
    softmax_k<<<dim3(512, NB), 256>>>();
    softmax_q<<<dim3(L / 256, NHEADS, NB), 256>>>();
    zero_ctx<<<(NB * NHEADS * CH * CH) / 256, 256>>>();
    ctx_kernel<<<dim3(NB * NHEADS, 8), 256>>>();
    a_kernel<<<dim3(NB * NHEADS, D / 64), 256>>>(Wout);
    gemm_out_tc<<<dim3(L / 128, D / 128, NB), 256>>>(bout, y);
}